// round 17
// baseline (speedup 1.0000x reference)
#include <cuda_runtime.h>
#include <cuda_fp16.h>

#define R_ 8
#define K_ 10
#define D_ 256
#define DL_ 10
#define B_ 4096
#define MT 64
#define NT_ 64          // number of row tiles = B_/MT
#define ZSTR 132        // k-slots of 12 floats, stride 132

// ---------------- device scratch (static, no allocs) ----------------
__device__ float    g_P[R_ * K_ * 56];            // packed symmetric Gram
__device__ unsigned g_u1h[R_ * 13 * 16 * 32 * 2]; // GEMM1 B frags fp16 [r][t13][kb16][lane] uint2
__device__ unsigned g_u2h[R_ * 32 * 7 * 32 * 2];  // GEMM2 B frags fp16 [r][t32][kb7][lane] uint2

__device__ __forceinline__ unsigned h2u(float lo, float hi) {
    __half2 h = __floats2half2_rn(lo, hi);
    return *reinterpret_cast<unsigned*>(&h);
}
__device__ __forceinline__ void mma16(float* c, unsigned a0, unsigned a1,
                                      unsigned a2, unsigned a3,
                                      unsigned b0, unsigned b1) {
    asm volatile(
        "mma.sync.aligned.m16n8k16.row.col.f32.f16.f16.f32 "
        "{%0,%1,%2,%3}, {%4,%5,%6,%7}, {%8,%9}, {%0,%1,%2,%3};"
        : "+f"(c[0]), "+f"(c[1]), "+f"(c[2]), "+f"(c[3])
        : "r"(a0), "r"(a1), "r"(a2), "r"(a3), "r"(b0), "r"(b1));
}

// ---------------- fused prep kernel (U-only) ----------------
// blocks [0,80):    gram   rk  = b
// blocks [80,184):  upack1 idx = b-80   (r*13+t13)
// blocks [184,440): upack2 idx = b-184  (r*32+t32)
__global__ void __launch_bounds__(256)
ks_prep(const float* __restrict__ Us) {
    const int b = blockIdx.x, tidb = threadIdx.x;

    if (b < 80) {                       // ---- gram ----
        __shared__ float u[D_ * DL_];
        __shared__ float G[DL_ * DL_];
        const int rk = b;
        const float* Up = Us + (size_t)rk * D_ * DL_;
        for (int i = tidb; i < D_ * DL_; i += 256) u[i] = Up[i];
        __syncthreads();
        if (tidb < DL_ * DL_) {
            const int i = tidb / DL_, j = tidb % DL_;
            float s = 0.0f;
            #pragma unroll 8
            for (int dd = 0; dd < D_; dd++) s += u[dd * DL_ + i] * u[dd * DL_ + j];
            G[tidb] = s;
        }
        __syncthreads();
        if (tidb < 55) {
            int tt = tidb, i = 0;
            while (tt >= DL_ - i) { tt -= DL_ - i; i++; }
            const int j = i + tt;
            g_P[rk * 56 + tidb] = G[i * DL_ + j] * (i == j ? 1.0f : 2.0f);
        }
    } else if (b < 184) {               // ---- upack1 (fp16 B frags, GEMM1) ----
        const int idx = b - 80;
        const int r = idx / 13, t13 = idx % 13;
        for (int e = tidb; e < 512; e += 256) {
            const int lane = e & 31, kb = e >> 5;
            const int g = lane >> 2, tig = lane & 3;
            const int j = t13 * 8 + g;
            uint2 v = make_uint2(0u, 0u);
            if (j < 100) {
                const int k0 = kb * 16 + tig * 2;
                const float* up = Us + ((size_t)(r * 10 + j / 10) * D_) * 10 + (j % 10);
                v.x = h2u(up[(size_t)k0 * 10],       up[(size_t)(k0 + 1) * 10]);
                v.y = h2u(up[(size_t)(k0 + 8) * 10], up[(size_t)(k0 + 9) * 10]);
            }
            ((uint2*)g_u1h)[((r * 13 + t13) * 16 + kb) * 32 + lane] = v;
        }
    } else {                            // ---- upack2 (fp16 B frags, GEMM2) ----
        const int idx = b - 184;
        const int r = idx >> 5, t32 = idx & 31;
        if (tidb < 224) {
            const int lane = tidb & 31, kb = tidb >> 5;
            const int g = lane >> 2, tig = lane & 3;
            const int n = t32 * 8 + g;
            const int j0 = kb * 16 + tig * 2;
            float f[4];
            const int js[4] = {j0, j0 + 1, j0 + 8, j0 + 9};
            #pragma unroll
            for (int q = 0; q < 4; q++) {
                const int j = js[q];
                f[q] = (j < 100)
                    ? Us[((size_t)(r * 10 + j / 10) * D_ + n) * 10 + (j % 10)]
                    : 0.0f;
            }
            uint2 v;
            v.x = h2u(f[0], f[1]);
            v.y = h2u(f[2], f[3]);
            ((uint2*)g_u2h)[((r * 32 + t32) * 7 + kb) * 32 + lane] = v;
        }
    }
}

// ---------------- smem layout (bytes) ----------------
// Phase A (staging + GEMM1 reads): SA 0..32768, SB 32768..86016
// Phase B overlay: ZW 0..33792, W2 33792..48128, U2S 48128..105472 (FULL 57344B)
// GP lives beyond both phases: 105472..107712
#define SM_STA  0          // A stage: 2048 uint4 = 32768
#define SM_STB  32768      // B1 stage: 6656 uint2 = 53248
#define SM_ZW   0          // overlay: 64 x 132 x 4 = 33792
#define SM_W2   33792      // overlay: W fp16 frags = 14336
#define SM_U2S  48128      // overlay: U2 fp16 frags = 57344 (3584 uint4)
#define SM_GP   105472     // 2240
#define SMEM_TOTAL 107712  // x2 CTAs = 210.4 KB

// ---------------- main fused kernel (2 CTAs/SM) ----------------
extern "C" __global__ void __launch_bounds__(256, 2)
ks_main(const float* __restrict__ x, float* __restrict__ out) {
    extern __shared__ __align__(128) char smem[];
    const int tid = threadIdx.x, wid = tid >> 5, lane = tid & 31;
    const int g = lane >> 2, tig = lane & 3;
    const int r = blockIdx.y, tile = blockIdx.x, b0 = tile * MT;
    const int mw = wid >> 2, nw = wid & 3;

    float* ZW  = (float*)(smem + SM_ZW);
    float* GP  = (float*)(smem + SM_GP);

    for (int i = tid; i < 560; i += 256) GP[i] = g_P[r * 560 + i];

    // ======== stage GEMM1 operands ========
    // A: in-CTA fp16 fragment conversion straight from x (no intermediate)
    {
        uint4* SA = (uint4*)(smem + SM_STA);
        const int blk = wid & 3;                 // constant per thread
        const int hi  = tid >> 7;
        const int rA = b0 + blk * 16 + g;
        const float* pR = x + (size_t)rA * D_ + tig * 2;
        #pragma unroll
        for (int it = 0; it < 8; it++) {
            const int kb = it * 2 + hi;
            const float* pA = pR + kb * 16;
            const float* pB = pA + 8 * D_;
            uint4 v;
            v.x = h2u(pA[0], pA[1]);
            v.y = h2u(pB[0], pB[1]);
            v.z = h2u(pA[8], pA[9]);
            v.w = h2u(pB[8], pB[9]);
            SA[kb * 128 + blk * 32 + lane] = v;
        }
        // B1 frags: flat burst copy
        const uint4* U1s = (const uint4*)g_u1h + (size_t)r * 3328;
        uint4* SB = (uint4*)(smem + SM_STB);
        #pragma unroll
        for (int it = 0; it < 13; it++) SB[it * 256 + tid] = U1s[it * 256 + tid];
    }
    __syncthreads();

    // ======== GEMM1: z[64][100] = x[64][256] @ Ucat  (all-smem operands) ========
    float acc[2][4][4];
    int tv[4];
    {
        const uint4* SA4 = (const uint4*)(smem + SM_STA);
        const uint2* SB2 = (const uint2*)(smem + SM_STB);
        #pragma unroll
        for (int nt = 0; nt < 4; nt++) tv[nt] = (nw + 4 * nt) < 13;

        #pragma unroll
        for (int mt = 0; mt < 2; mt++)
            #pragma unroll
            for (int nt = 0; nt < 4; nt++)
                #pragma unroll
                for (int q = 0; q < 4; q++) acc[mt][nt][q] = 0.0f;

        #pragma unroll
        for (int kb = 0; kb < 16; kb++) {
            uint4 a[2];
            #pragma unroll
            for (int mt = 0; mt < 2; mt++)
                a[mt] = SA4[(kb * 4 + mw * 2 + mt) * 32 + lane];
            uint2 bfr[4];
            #pragma unroll
            for (int nt = 0; nt < 4; nt++)
                if (tv[nt]) bfr[nt] = SB2[((nw + 4 * nt) * 16 + kb) * 32 + lane];
            #pragma unroll
            for (int nt = 0; nt < 4; nt++) {
                if (!tv[nt]) continue;
                #pragma unroll
                for (int mt = 0; mt < 2; mt++)
                    mma16(acc[mt][nt], a[mt].x, a[mt].y, a[mt].z, a[mt].w,
                          bfr[nt].x, bfr[nt].y);
            }
        }
    }
    __syncthreads();   // all stage reads done; region becomes ZW + W2 + U2S

    // ======== ZW fragment stores (into overlay region) ========
    #pragma unroll
    for (int mt = 0; mt < 2; mt++)
        #pragma unroll
        for (int nt = 0; nt < 4; nt++)
            if (tv[nt]) {
                const int col = (nw + 4 * nt) * 8 + 2 * tig;   // even
                const int ks = col / 10, d = col - ks * 10;
                const int r0 = mw * 32 + mt * 16 + g;
                *(float2*)(ZW + r0 * ZSTR + ks * 12 + d) =
                    make_float2(acc[mt][nt][0], acc[mt][nt][1]);
                *(float2*)(ZW + (r0 + 8) * ZSTR + ks * 12 + d) =
                    make_float2(acc[mt][nt][2], acc[mt][nt][3]);
            }
    __syncthreads();

    // ======== merged: logits + softmax (quad shuffles) + fp16 w-frag pack ========
    {
        const int row = tid >> 2, sub = tid & 3;
        const int nk = (sub < 2) ? 3 : 2;        // k = sub, sub+4, sub+8(sub<2)
        const float* zR = ZW + row * ZSTR;
        const int blk = row >> 4, hh = (row >> 3) & 1, gg = row & 7;

        float z[3][10], lg[3], ex[3];
        float m = -1e30f;
        #pragma unroll
        for (int i = 0; i < 3; i++) {
            if (i >= nk) continue;
            const int k = sub + 4 * i;
            const float4 z0 = *(const float4*)(zR + k * 12);
            const float4 z1 = *(const float4*)(zR + k * 12 + 4);
            const float2 z2 = *(const float2*)(zR + k * 12 + 8);
            z[i][0] = z0.x; z[i][1] = z0.y; z[i][2] = z0.z; z[i][3] = z0.w;
            z[i][4] = z1.x; z[i][5] = z1.y; z[i][6] = z1.z; z[i][7] = z1.w;
            z[i][8] = z2.x; z[i][9] = z2.y;
            float s1 = 0.0f;
            #pragma unroll
            for (int d = 0; d < DL_; d++) s1 += z[i][d] * z[i][d];
            const float* Pk = GP + k * 56;
            float s2 = 0.0f; int tt = 0;
            #pragma unroll
            for (int i2 = 0; i2 < DL_; i2++)
                #pragma unroll
                for (int j2 = i2; j2 < DL_; j2++) { s2 += Pk[tt] * z[i][i2] * z[i][j2]; tt++; }
            lg[i] = 10.0f * s1 - 5.0f * s2;
            m = fmaxf(m, lg[i]);
        }
        m = fmaxf(m, __shfl_xor_sync(0xffffffffu, m, 1));
        m = fmaxf(m, __shfl_xor_sync(0xffffffffu, m, 2));
        float s = 0.0f;
        #pragma unroll
        for (int i = 0; i < 3; i++)
            if (i < nk) { ex[i] = __expf(lg[i] - m); s += ex[i]; }
        s += __shfl_xor_sync(0xffffffffu, s, 1);
        s += __shfl_xor_sync(0xffffffffu, s, 2);
        const float inv = 1.0f / s;

        // write w = c*z as fp16 into lane-linear frag layout
        #pragma unroll
        for (int i = 0; i < 3; i++) {
            if (i >= nk) continue;
            const int k = sub + 4 * i;
            const float c = ex[i] * inv;
            #pragma unroll
            for (int d = 0; d < DL_; d++) {
                const int j = k * 10 + d;
                const int kb = j >> 4, c2 = j & 15;
                const int tg = (c2 & 7) >> 1, sel = c2 >> 3, w1 = c2 & 1;
                const unsigned addr = SM_W2 +
                    ((((blk * 2 + hh) * 7 + kb) * 32 + gg * 4 + tg) << 3) +
                    sel * 4 + w1 * 2;
                *(__half*)(smem + addr) = __float2half_rn(c * z[i][d]);
            }
        }
        #pragma unroll
        for (int i = 0; i < 3; i++) {           // zero-pad j = 100..111
            const int j = 100 + sub * 3 + i;
            const int kb = j >> 4, c2 = j & 15;
            const int tg = (c2 & 7) >> 1, sel = c2 >> 3, w1 = c2 & 1;
            const unsigned addr = SM_W2 +
                ((((blk * 2 + hh) * 7 + kb) * 32 + gg * 4 + tg) << 3) +
                sel * 4 + w1 * 2;
            *(__half*)(smem + addr) = __float2half_rn(0.0f);
        }
    }

    // ======== stage GEMM2 B frags into smem (FULL slab; overlaps softmax) ========
    {
        const uint4* U2g = (const uint4*)g_u2h + (size_t)r * 3584;
        uint4* U2S = (uint4*)(smem + SM_U2S);
        #pragma unroll
        for (int it = 0; it < 14; it++) U2S[it * 256 + tid] = U2g[it * 256 + tid];
    }
    __syncthreads();

    // ======== GEMM2: out[64][256] = w[64][112] @ Ucat^T  (all-smem operands) ========
    float acc2[2][8][4];
    {
        #pragma unroll
        for (int mt = 0; mt < 2; mt++)
            #pragma unroll
            for (int nt = 0; nt < 8; nt++)
                #pragma unroll
                for (int q = 0; q < 4; q++) acc2[mt][nt][q] = 0.0f;

        const uint2* WF = (const uint2*)(smem + SM_W2);
        const uint2* U2 = (const uint2*)(smem + SM_U2S) + (nw * 8) * (7 * 32) + lane;

        #pragma unroll
        for (int kb = 0; kb < 7; kb++) {
            uint2 ah[2][2];
            #pragma unroll
            for (int mt = 0; mt < 2; mt++)
                #pragma unroll
                for (int h = 0; h < 2; h++)
                    ah[mt][h] = WF[(((mw * 2 + mt) * 2 + h) * 7 + kb) * 32 + g * 4 + tig];
            #pragma unroll
            for (int nt = 0; nt < 8; nt++) {
                const uint2 b = U2[(nt * 7 + kb) * 32];
                #pragma unroll
                for (int mt = 0; mt < 2; mt++)
                    mma16(acc2[mt][nt], ah[mt][0].x, ah[mt][1].x,
                          ah[mt][0].y, ah[mt][1].y, b.x, b.y);
            }
        }
    }

    // ======== epilogue: direct STG.64 from fragments (32B chunks per quad) ========
    {
        float* op = out + ((size_t)r * B_ + b0) * D_;
        #pragma unroll
        for (int mt = 0; mt < 2; mt++) {
            const int r0 = mw * 32 + mt * 16 + g;
            #pragma unroll
            for (int nt = 0; nt < 8; nt++) {
                const int col = (nw * 8 + nt) * 8 + 2 * tig;
                *(float2*)(op + r0 * D_ + col) =
                    make_float2(acc2[mt][nt][0], acc2[mt][nt][1]);
                *(float2*)(op + (r0 + 8) * D_ + col) =
                    make_float2(acc2[mt][nt][2], acc2[mt][nt][3]);
            }
        }
    }
}

extern "C" void kernel_launch(void* const* d_in, const int* in_sizes, int n_in,
                              void* d_out, int out_size) {
    const float* x  = (const float*)d_in[0];   // (4096, 256)
    const float* Us = (const float*)d_in[1];   // (8, 10, 256, 10)
    float* out = (float*)d_out;                // (8, 4096, 256)

    cudaFuncSetAttribute(ks_main, cudaFuncAttributeMaxDynamicSharedMemorySize,
                         SMEM_TOTAL);

    ks_prep<<<440, 256>>>(Us);

    dim3 grid(NT_, R_);
    ks_main<<<grid, 256, SMEM_TOTAL>>>(x, out);
}